// round 9
// baseline (speedup 1.0000x reference)
#include <cuda_runtime.h>
#include <cuda_bf16.h>
#include <math.h>

// ---------------------------------------------------------------------------
// DeepJ biaxial LSTM.  B=1024, N=48, TU=256, NU=128, IN_T=50 (pad 64).
//   - time-axis LSTM layers: single step h=c=0 => feed-forward gate GEMMs
//     (Whh dead, f-gate dead).
//   - Those GEMMs run as PLAIN bf16 GEMMs on mma.sync m16n8k16 (tcgen05 is
//     rejected by the harness's PTX target sm_103).  fp32 precision is
//     recovered by bf16 hi/lo splitting folded into K at prep time:
//     A' = [Ah|Al|Ah], B' = [Wh|Wh|Wl]  => AhWh + AlWh + AhWl in one GEMM.
//   - note-axis scan: persistent scalar fp32 (unchanged, known-good).
// ---------------------------------------------------------------------------

#define BB 1024
#define NN 48
#define MM (BB * NN)   // 49152

typedef __nv_bfloat16 bf16;

// scratch (device globals: allocation-free)
__device__ bf16  g_ac0[MM * 192];      // rnn_in split-concat (K'=192)
__device__ bf16  g_ac1[MM * 768];      // h1 split-concat     (K'=768)
__device__ bf16  g_ac2[MM * 768];      // feats split-concat  (K'=768)
__device__ float g_raw[MM * 768];      // raw gate scratch
__device__ bf16  g_w0c[768 * 192];     // t_Wih0 live-gate split-concat
__device__ bf16  g_w1c[768 * 768];     // t_Wih1 live-gate split-concat
__device__ bf16  g_w2c[512 * 768];     // n_Wih0[:, :256] split-concat
__device__ float g_wc[512];            // n_Wih0[:, 256] (cond column)
__device__ float g_xw[MM * 512];

__device__ __forceinline__ float sigf(float x) { return 1.0f / (1.0f + expf(-x)); }

// ----------------------------- prep kernels -------------------------------

__device__ __forceinline__ void split3(float v, bf16* p0, bf16* p1, bf16* p2) {
    bf16 hh = __float2bfloat16(v);
    bf16 hl = __float2bfloat16(v - __bfloat162float(hh));
    *p0 = hh; *p1 = hl; *p2 = hh;          // activations: [hi | lo | hi]
}
__device__ __forceinline__ void splitw(float v, bf16* p0, bf16* p1, bf16* p2) {
    bf16 hh = __float2bfloat16(v);
    bf16 hl = __float2bfloat16(v - __bfloat162float(hh));
    *p0 = hh; *p1 = hh; *p2 = hl;          // weights: [hi | hi | lo]
}

__global__ void build_ac0(const float* __restrict__ note) {
    int idx = blockIdx.x * blockDim.x + threadIdx.x;   // MM * 64
    if (idx >= MM * 64) return;
    int f = idx & 63;
    int m = idx >> 6;
    int b = m / NN, n = m % NN;
    float v = 0.0f;
    if (f == 0) {
        v = (float)n * (1.0f / (float)NN);
    } else if (f < 13) {
        v = ((f - 1) == (n % 12)) ? 1.0f : 0.0f;
    } else if (f < 38) {
        int p = n + (f - 13) - 12;
        v = (p >= 0 && p < NN) ? note[b * NN + p] : 0.0f;
    } else if (f < 50) {
        const float* nb = note + b * NN + (f - 38) * 4;
        v = nb[0] + nb[1] + nb[2] + nb[3];
    }
    size_t o = (size_t)m * 192 + f;
    split3(v, &g_ac0[o], &g_ac0[o + 64], &g_ac0[o + 128]);
}

// t_Wih0 (1024 x 50) -> live gates {i,g,o} = gate rows {0,2,3}, K pad 64
__global__ void build_w0c(const float* __restrict__ w) {
    int idx = blockIdx.x * blockDim.x + threadIdx.x;   // 768 * 64
    if (idx >= 768 * 64) return;
    int k = idx & 63, r = idx >> 6;
    int u = r & 255, g3 = r >> 8;
    int ga = (g3 == 0) ? 0 : g3 + 1;
    float v = (k < 50) ? w[(size_t)(ga * 256 + u) * 50 + k] : 0.0f;
    size_t o = (size_t)r * 192 + k;
    splitw(v, &g_w0c[o], &g_w0c[o + 64], &g_w0c[o + 128]);
}

// t_Wih1 (1024 x 256) -> live gates, K'=768
__global__ void build_w1c(const float* __restrict__ w) {
    int idx = blockIdx.x * blockDim.x + threadIdx.x;   // 768 * 256
    if (idx >= 768 * 256) return;
    int k = idx & 255, r = idx >> 8;
    int u = r & 255, g3 = r >> 8;
    int ga = (g3 == 0) ? 0 : g3 + 1;
    float v = w[(size_t)(ga * 256 + u) * 256 + k];
    size_t o = (size_t)r * 768 + k;
    splitw(v, &g_w1c[o], &g_w1c[o + 256], &g_w1c[o + 512]);
}

// n_Wih0 (512 x 257) -> all 4 gates, K'=768 ; also extracts cond column
__global__ void build_w2c(const float* __restrict__ w) {
    int idx = blockIdx.x * blockDim.x + threadIdx.x;   // 512 * 256
    if (idx >= 512 * 256) return;
    int k = idx & 255, r = idx >> 8;
    float v = w[(size_t)r * 257 + k];
    size_t o = (size_t)r * 768 + k;
    splitw(v, &g_w2c[o], &g_w2c[o + 256], &g_w2c[o + 512]);
    if (k == 0) g_wc[r] = w[(size_t)r * 257 + 256];
}

// pointwise: raw gates (i,g,o blocks of 256) -> h, emitted split-concat bf16
__global__ void act_kernel(const float* __restrict__ raw,
                           const float* __restrict__ b,
                           bf16* __restrict__ ac) {
    int idx = blockIdx.x * blockDim.x + threadIdx.x;   // MM * 256
    if (idx >= MM * 256) return;
    int u = idx & 255;
    size_t m = (size_t)(idx >> 8);
    float gi = raw[m * 768 + u]       + b[u];
    float gg = raw[m * 768 + 256 + u] + b[512 + u];
    float go = raw[m * 768 + 512 + u] + b[768 + u];
    float h = sigf(go) * tanhf(sigf(gi) * tanhf(gg));
    size_t o = m * 768 + u;
    split3(h, &ac[o], &ac[o + 256], &ac[o + 512]);
}

// ------------------------- bf16 mma.sync gate GEMM ------------------------
// C[M x N] = A'[M x K'] @ B'[N x K']^T, bf16 in, fp32 accum.
// Block tile 128 x 64, 8 warps (4m x 2n), K chunks of 32.
// Staging [row][k] stride 40 bf16 => conflict-free b32 fragment loads.

__device__ __forceinline__ void mma16(float c[4], const unsigned a[4],
                                      const unsigned b[2]) {
    asm volatile(
        "mma.sync.aligned.m16n8k16.row.col.f32.bf16.bf16.f32 "
        "{%0,%1,%2,%3}, {%4,%5,%6,%7}, {%8,%9}, {%0,%1,%2,%3};"
        : "+f"(c[0]), "+f"(c[1]), "+f"(c[2]), "+f"(c[3])
        : "r"(a[0]), "r"(a[1]), "r"(a[2]), "r"(a[3]), "r"(b[0]), "r"(b[1]));
}

__global__ __launch_bounds__(256)
void gemm_bf(const bf16* __restrict__ A, const bf16* __restrict__ B,
             float* __restrict__ C, int Kp, int ldc) {
    __shared__ __align__(16) char smem[128 * 68 * 4];   // dump >= tiles
    bf16* sA = (bf16*)smem;                  // [128][40]
    bf16* sB = (bf16*)(smem + 10240);        // [64][40]

    const int t = threadIdx.x;
    const int lane = t & 31, wid = t >> 5;
    const int wm = wid & 3, wn = wid >> 2;
    const int gid = lane >> 2, tid4 = lane & 3;
    const int m0 = blockIdx.x * 128;
    const int c0 = blockIdx.y * 64;

    float acc[2][4][4];
#pragma unroll
    for (int mi = 0; mi < 2; mi++)
#pragma unroll
        for (int ni = 0; ni < 4; ni++)
#pragma unroll
            for (int q = 0; q < 4; q++) acc[mi][ni][q] = 0.0f;

    // global-load indices: A 128 rows x 4 uint4 (2/thread), B 64 x 4 (1/thread)
    const int ar0 = t >> 2, ac0 = (t & 3) * 8;            // + 64 rows for slot 1
    const int br0 = t >> 2, bc0 = (t & 3) * 8;            // threads 0..255 -> 64 rows? 
    // B: 64 rows x 4 uint4 = 256 slots, one per thread: row = t>>2, col8 = (t&3)*8

    uint4 pa0, pa1, pb;
    // prologue: chunk 0
    pa0 = *(const uint4*)(A + (size_t)(m0 + ar0) * Kp + ac0);
    pa1 = *(const uint4*)(A + (size_t)(m0 + ar0 + 64) * Kp + ac0);
    pb  = *(const uint4*)(B + (size_t)(c0 + br0) * Kp + bc0);

    const int nchunks = Kp >> 5;
    for (int kc = 0; kc < nchunks; kc++) {
        *(uint4*)&sA[ar0 * 40 + ac0]        = pa0;
        *(uint4*)&sA[(ar0 + 64) * 40 + ac0] = pa1;
        *(uint4*)&sB[br0 * 40 + bc0]        = pb;
        __syncthreads();

        if (kc + 1 < nchunks) {
            int ko = (kc + 1) * 32;
            pa0 = *(const uint4*)(A + (size_t)(m0 + ar0) * Kp + ko + ac0);
            pa1 = *(const uint4*)(A + (size_t)(m0 + ar0 + 64) * Kp + ko + ac0);
            pb  = *(const uint4*)(B + (size_t)(c0 + br0) * Kp + ko + bc0);
        }

#pragma unroll
        for (int kh = 0; kh < 2; kh++) {
            const int kb = kh * 16;
            unsigned Af[2][4], Bf[4][2];
#pragma unroll
            for (int mi = 0; mi < 2; mi++) {
                int r = wm * 32 + mi * 16 + gid;
                Af[mi][0] = *(const unsigned*)&sA[r * 40 + kb + tid4 * 2];
                Af[mi][1] = *(const unsigned*)&sA[(r + 8) * 40 + kb + tid4 * 2];
                Af[mi][2] = *(const unsigned*)&sA[r * 40 + kb + tid4 * 2 + 8];
                Af[mi][3] = *(const unsigned*)&sA[(r + 8) * 40 + kb + tid4 * 2 + 8];
            }
#pragma unroll
            for (int ni = 0; ni < 4; ni++) {
                int c = wn * 32 + ni * 8 + gid;
                Bf[ni][0] = *(const unsigned*)&sB[c * 40 + kb + tid4 * 2];
                Bf[ni][1] = *(const unsigned*)&sB[c * 40 + kb + tid4 * 2 + 8];
            }
#pragma unroll
            for (int mi = 0; mi < 2; mi++)
#pragma unroll
                for (int ni = 0; ni < 4; ni++)
                    mma16(acc[mi][ni], Af[mi], Bf[ni]);
        }
        __syncthreads();
    }

    // dump accumulators to smem [128][68], then coalesced float4 stores
    float* sd = (float*)smem;
#pragma unroll
    for (int mi = 0; mi < 2; mi++)
#pragma unroll
        for (int ni = 0; ni < 4; ni++) {
            int r = wm * 32 + mi * 16 + gid;
            int c = wn * 32 + ni * 8 + tid4 * 2;
            sd[r * 68 + c]           = acc[mi][ni][0];
            sd[r * 68 + c + 1]       = acc[mi][ni][1];
            sd[(r + 8) * 68 + c]     = acc[mi][ni][2];
            sd[(r + 8) * 68 + c + 1] = acc[mi][ni][3];
        }
    __syncthreads();

#pragma unroll
    for (int j = 0; j < 8; j++) {
        int i = j * 256 + t;                 // 2048 float4 slots
        int r = i >> 4, c4 = i & 15;
        *(float4*)&C[(size_t)(m0 + r) * ldc + c0 + c4 * 4] =
            *(float4*)&sd[r * 68 + c4 * 4];
    }
}

// ------------------------------ note-axis scan -----------------------------
// (unchanged, known-good)  128 blocks x 8 batches, 256 threads.

__device__ __forceinline__ void load_wtile_regs(float4 pre[8],
                                                const float* __restrict__ W,
                                                int kt, int t) {
#pragma unroll
    for (int i = 0; i < 8; i++) {
        int lin = t + 256 * i;
        int r = lin >> 2, k4 = lin & 3;
        pre[i] = *(const float4*)&W[r * 128 + kt + k4 * 4];
    }
}

__device__ __forceinline__ void sts_wtile(float* dst, const float4 pre[8], int t) {
#pragma unroll
    for (int i = 0; i < 8; i++) {
        int lin = t + 256 * i;
        int r = lin >> 2, k4 = lin & 3;
        *(float4*)&dst[r * 20 + k4 * 4] = pre[i];
    }
}

__device__ __forceinline__ void accum_tile(float acc[4][4], const float* sWt,
                                           const float* sH, int kt, int u, int bp) {
#pragma unroll
    for (int kk = 0; kk < 16; kk += 4) {
        float4 wv[4];
#pragma unroll
        for (int g = 0; g < 4; g++)
            wv[g] = *(const float4*)&sWt[(g * 128 + u) * 20 + kk];
#pragma unroll
        for (int b = 0; b < 4; b++) {
            float4 hv = *(const float4*)&sH[(bp * 4 + b) * 128 + kt + kk];
#pragma unroll
            for (int g = 0; g < 4; g++) {
                acc[b][g] += hv.x * wv[g].x;
                acc[b][g] += hv.y * wv[g].y;
                acc[b][g] += hv.z * wv[g].z;
                acc[b][g] += hv.w * wv[g].w;
            }
        }
    }
}

__device__ __forceinline__ void gemm_pass(float acc[4][4],
                                          const float* __restrict__ W,
                                          const float* sH, float* sW,
                                          int t, int u, int bp) {
    float4 pre[8];
    load_wtile_regs(pre, W, 0, t);
    sts_wtile(sW, pre, t);
    __syncthreads();
    for (int it = 0; it < 8; it++) {
        float* cur = sW + (it & 1) * 10240;
        if (it < 7) load_wtile_regs(pre, W, (it + 1) * 16, t);
        accum_tile(acc, cur, sH, it * 16, u, bp);
        if (it < 7) sts_wtile(sW + ((it + 1) & 1) * 10240, pre, t);
        __syncthreads();
    }
}

__global__ __launch_bounds__(256, 1)
void scan_kernel(const float* __restrict__ targets,
                 const float* __restrict__ Whh0,
                 const float* __restrict__ nb0,
                 const float* __restrict__ Wih1,
                 const float* __restrict__ Whh1,
                 const float* __restrict__ nb1,
                 const float* __restrict__ outW,
                 const float* __restrict__ outb,
                 float* __restrict__ out) {
    extern __shared__ float sh[];
    float* sW  = sh;              // 2 x 512 x 20 = 20480
    float* sH1 = sh + 20480;      // 8 x 128
    float* sH2 = sH1 + 1024;      // 8 x 128
    float* sWo = sH2 + 1024;      // 128

    const int t = threadIdx.x;
    const int u = t & 127, bp = t >> 7;
    const int B0 = blockIdx.x * 8;

    if (t < 128) sWo[t] = outW[t];
    for (int i = t; i < 2048; i += 256) sH1[i] = 0.0f;

    float c1[4] = {0, 0, 0, 0}, c2[4] = {0, 0, 0, 0};
    float b0r[4], b1r[4], wcr[4];
#pragma unroll
    for (int g = 0; g < 4; g++) {
        b0r[g] = nb0[g * 128 + u];
        b1r[g] = nb1[g * 128 + u];
        wcr[g] = g_wc[g * 128 + u];
    }
    const float ob = outb[0];
    __syncthreads();

    for (int n = 0; n < NN; n++) {
        float acc[4][4];
#pragma unroll
        for (int b = 0; b < 4; b++) {
            int bg = B0 + bp * 4 + b;
            float cond = (n == 0) ? 0.0f : targets[bg * NN + n - 1];
            size_t m = (size_t)bg * NN + n;
#pragma unroll
            for (int g = 0; g < 4; g++)
                acc[b][g] = g_xw[m * 512 + g * 128 + u] + b0r[g] + cond * wcr[g];
        }
        gemm_pass(acc, Whh0, sH1, sW, t, u, bp);

        float h1n[4];
#pragma unroll
        for (int b = 0; b < 4; b++) {
            float cc = sigf(acc[b][1]) * c1[b] + sigf(acc[b][0]) * tanhf(acc[b][2]);
            c1[b] = cc;
            h1n[b] = sigf(acc[b][3]) * tanhf(cc);
        }
#pragma unroll
        for (int b = 0; b < 4; b++) sH1[(bp * 4 + b) * 128 + u] = h1n[b];
        __syncthreads();

        float acc2[4][4];
#pragma unroll
        for (int b = 0; b < 4; b++)
#pragma unroll
            for (int g = 0; g < 4; g++) acc2[b][g] = b1r[g];
        gemm_pass(acc2, Wih1, sH1, sW, t, u, bp);
        gemm_pass(acc2, Whh1, sH2, sW, t, u, bp);

        float h2n[4];
#pragma unroll
        for (int b = 0; b < 4; b++) {
            float cc = sigf(acc2[b][1]) * c2[b] + sigf(acc2[b][0]) * tanhf(acc2[b][2]);
            c2[b] = cc;
            h2n[b] = sigf(acc2[b][3]) * tanhf(cc);
        }
#pragma unroll
        for (int b = 0; b < 4; b++) sH2[(bp * 4 + b) * 128 + u] = h2n[b];
        __syncthreads();

        int w = t >> 5, lane = t & 31;
        float p = 0.0f;
#pragma unroll
        for (int j = 0; j < 4; j++)
            p += sH2[w * 128 + lane + 32 * j] * sWo[lane + 32 * j];
#pragma unroll
        for (int off = 16; off; off >>= 1)
            p += __shfl_down_sync(0xffffffffu, p, off);
        if (lane == 0) out[(B0 + w) * NN + n] = sigf(p + ob);
    }
}

// --------------------------------- launch ---------------------------------

extern "C" void kernel_launch(void* const* d_in, const int* in_sizes, int n_in,
                              void* d_out, int out_size) {
    (void)in_sizes; (void)n_in; (void)out_size;
    const float* note    = (const float*)d_in[0];
    const float* targets = (const float*)d_in[1];
    const float* tWih0   = (const float*)d_in[2];
    const float* tb0     = (const float*)d_in[4];
    const float* tWih1   = (const float*)d_in[5];
    const float* tb1     = (const float*)d_in[7];
    const float* nWih0   = (const float*)d_in[8];
    const float* nWhh0   = (const float*)d_in[9];
    const float* nb0     = (const float*)d_in[10];
    const float* nWih1   = (const float*)d_in[11];
    const float* nWhh1   = (const float*)d_in[12];
    const float* nb1     = (const float*)d_in[13];
    const float* outW    = (const float*)d_in[14];
    const float* outb    = (const float*)d_in[15];
    float* out = (float*)d_out;

    bf16 *p_ac0, *p_ac1, *p_ac2, *p_w0c, *p_w1c, *p_w2c;
    float *p_raw, *p_xw;
    cudaGetSymbolAddress((void**)&p_ac0, g_ac0);
    cudaGetSymbolAddress((void**)&p_ac1, g_ac1);
    cudaGetSymbolAddress((void**)&p_ac2, g_ac2);
    cudaGetSymbolAddress((void**)&p_raw, g_raw);
    cudaGetSymbolAddress((void**)&p_w0c, g_w0c);
    cudaGetSymbolAddress((void**)&p_w1c, g_w1c);
    cudaGetSymbolAddress((void**)&p_w2c, g_w2c);
    cudaGetSymbolAddress((void**)&p_xw,  g_xw);

    build_ac0<<<(MM * 64) / 256, 256>>>(note);
    build_w0c<<<(768 * 64) / 256, 256>>>(tWih0);
    build_w1c<<<(768 * 256) / 256, 256>>>(tWih1);
    build_w2c<<<(512 * 256) / 256, 256>>>(nWih0);

    // raw_g1 = rnn_in' @ w0c'^T     (K'=192, N=768)
    gemm_bf<<<dim3(384, 12), 256>>>(p_ac0, p_w0c, p_raw, 192, 768);
    act_kernel<<<(MM * 256) / 256, 256>>>(p_raw, tb0, p_ac1);
    // raw_g2 = h1' @ w1c'^T         (K'=768, N=768)
    gemm_bf<<<dim3(384, 12), 256>>>(p_ac1, p_w1c, p_raw, 768, 768);
    act_kernel<<<(MM * 256) / 256, 256>>>(p_raw, tb1, p_ac2);
    // g_xw = feats' @ w2c'^T        (K'=768, N=512, raw gates for the scan)
    gemm_bf<<<dim3(384, 8), 256>>>(p_ac2, p_w2c, p_xw, 768, 512);

    const int smemS = 22656 * (int)sizeof(float);  // 90624 B
    cudaFuncSetAttribute(scan_kernel, cudaFuncAttributeMaxDynamicSharedMemorySize, smemS);
    scan_kernel<<<128, 256, smemS>>>(targets, nWhh0, nb0, nWih1, nWhh1, nb1,
                                     outW, outb, out);
}